// round 16
// baseline (speedup 1.0000x reference)
#include <cuda_runtime.h>

// mailbox: [N=50000, DEG=32, FEAT=128] float32 -> out[n][f] = mean over deg.
//
// Pure HBM-bound stream, ~845MB, zero reuse. Converged design: one thread per
// (node, float4-col); warp = exactly one 512B neighbor row -> every LDG.128 a
// full coalesced line; fully-unrolled deg loop, MLP=32/thread.
// __ldcg: read-once stream, L2-only (measured best vs .cs/default).
//
// Knob trend: block 256 -> 512 gave -1.4% (123.7us, 87.5% DRAM). R15 pushes
// the same lever: block=1024 (occ 2, same 2048 thr/SM, 1563 blocks = fewer
// dispatch events, longer uninterrupted per-SM streams), 4 accum chains.

#define N_NODES 50000
#define MAX_DEG 32
#define FEAT4   32                      // 128 floats / 4
#define TOTAL4  (N_NODES * FEAT4)       // 1,600,000 float4 outputs

__global__ void __launch_bounds__(1024, 2)
mean_agg_kernel(const float4* __restrict__ mailbox, float4* __restrict__ out) {
    int idx = blockIdx.x * blockDim.x + threadIdx.x;   // n * FEAT4 + f4
    if (idx >= TOTAL4) return;

    int n  = idx >> 5;          // / FEAT4
    int f4 = idx & 31;          // % FEAT4

    const float4* p = mailbox + ((long long)n * (MAX_DEG * FEAT4)) + f4;

    // four independent accumulator chains
    float4 a0 = make_float4(0.f, 0.f, 0.f, 0.f);
    float4 a1 = make_float4(0.f, 0.f, 0.f, 0.f);
    float4 a2 = make_float4(0.f, 0.f, 0.f, 0.f);
    float4 a3 = make_float4(0.f, 0.f, 0.f, 0.f);
#pragma unroll
    for (int d = 0; d < MAX_DEG; d += 4) {
        float4 v0 = __ldcg(&p[(d + 0) * FEAT4]);
        float4 v1 = __ldcg(&p[(d + 1) * FEAT4]);
        float4 v2 = __ldcg(&p[(d + 2) * FEAT4]);
        float4 v3 = __ldcg(&p[(d + 3) * FEAT4]);
        a0.x += v0.x; a0.y += v0.y; a0.z += v0.z; a0.w += v0.w;
        a1.x += v1.x; a1.y += v1.y; a1.z += v1.z; a1.w += v1.w;
        a2.x += v2.x; a2.y += v2.y; a2.z += v2.z; a2.w += v2.w;
        a3.x += v3.x; a3.y += v3.y; a3.z += v3.z; a3.w += v3.w;
    }

    const float inv = 1.0f / (float)MAX_DEG;
    float4 acc;
    acc.x = ((a0.x + a1.x) + (a2.x + a3.x)) * inv;
    acc.y = ((a0.y + a1.y) + (a2.y + a3.y)) * inv;
    acc.z = ((a0.z + a1.z) + (a2.z + a3.z)) * inv;
    acc.w = ((a0.w + a1.w) + (a2.w + a3.w)) * inv;
    out[idx] = acc;
}

extern "C" void kernel_launch(void* const* d_in, const int* in_sizes, int n_in,
                              void* d_out, int out_size) {
    const float4* mailbox = (const float4*)d_in[0];
    float4* out = (float4*)d_out;
    const int threads = 1024;
    const int blocks = (TOTAL4 + threads - 1) / threads;  // 1563
    mean_agg_kernel<<<blocks, threads>>>(mailbox, out);
}

// round 17
// speedup vs baseline: 1.0163x; 1.0163x over previous
#include <cuda_runtime.h>
#include <cstdint>

// mailbox: [N=50000, DEG=32, FEAT=128] float32 -> out[n][f] = mean over deg.
//
// Pure HBM-bound stream, ~845MB, zero reuse. Measured knob map:
//   block 256->125.4us | 512->123.7us (best) | 1024->127.5us (occ drop)
//   __ldcg > __ldcs > default ; flat grid > persistent grid
// R17: Blackwell 256-bit global loads (LDG.E.256 via ld.global.cg.v8.f32).
// One thread per (node, 8-float group): warp = 1024B = exactly 2 neighbor
// rows, fully coalesced; 16 v8 loads/thread instead of 32 v4 -> half the
// LSU dispatch + L1tex queue events per byte. Same DRAM traffic.

#define N_NODES 50000
#define MAX_DEG 32
#define FEAT    128
#define FEAT8   16                      // 128 floats / 8
#define TOTAL8  (N_NODES * FEAT8)       // 800,000 thread work items

__device__ __forceinline__ void ldg256_cg(const float* p, float* v) {
    asm volatile(
        "ld.global.cg.v8.f32 {%0,%1,%2,%3,%4,%5,%6,%7}, [%8];"
        : "=f"(v[0]), "=f"(v[1]), "=f"(v[2]), "=f"(v[3]),
          "=f"(v[4]), "=f"(v[5]), "=f"(v[6]), "=f"(v[7])
        : "l"(p));
}

__global__ void __launch_bounds__(512, 4)
mean_agg_kernel(const float* __restrict__ mailbox, float* __restrict__ out) {
    int idx = blockIdx.x * blockDim.x + threadIdx.x;   // n * FEAT8 + f8
    if (idx >= TOTAL8) return;

    int n  = idx >> 4;          // / FEAT8
    int f8 = idx & 15;          // % FEAT8

    const float* p = mailbox + ((long long)n * (MAX_DEG * FEAT)) + f8 * 8;

    float acc[8];
#pragma unroll
    for (int i = 0; i < 8; ++i) acc[i] = 0.f;

#pragma unroll
    for (int d = 0; d < MAX_DEG; ++d) {
        float v[8];
        ldg256_cg(p + d * FEAT, v);
#pragma unroll
        for (int i = 0; i < 8; ++i) acc[i] += v[i];
    }

    const float inv = 1.0f / (float)MAX_DEG;
    float4* o = (float4*)(out + (long long)idx * 8);
    float4 lo = make_float4(acc[0] * inv, acc[1] * inv, acc[2] * inv, acc[3] * inv);
    float4 hi = make_float4(acc[4] * inv, acc[5] * inv, acc[6] * inv, acc[7] * inv);
    o[0] = lo;
    o[1] = hi;
}

extern "C" void kernel_launch(void* const* d_in, const int* in_sizes, int n_in,
                              void* d_out, int out_size) {
    const float* mailbox = (const float*)d_in[0];
    float* out = (float*)d_out;
    const int threads = 512;
    const int blocks = (TOTAL8 + threads - 1) / threads;  // 1563
    mean_agg_kernel<<<blocks, threads>>>(mailbox, out);
}